// round 13
// baseline (speedup 1.0000x reference)
#include <cuda_runtime.h>
#include <math.h>

// Problem constants
#define BB 2
#define SS 2048
#define HID 2048
#define NH 16
#define NKV 4
#define DH 128
#define REP (NH / NKV)   // 4

// Scratch buffers
__device__ float g_q[(size_t)BB * SS * NH * DH];    // rope'd, scaled, tf32-rounded
__device__ float g_k[(size_t)BB * SS * NKV * DH];   // rope'd, tf32-rounded
__device__ float g_v[(size_t)BB * SS * NKV * DH];   // tf32-rounded
__device__ float g_o[(size_t)BB * SS * NH * DH];    // attn out, tf32-rounded
// tf32-rounded copies of inputs
__device__ float g_xc[(size_t)BB * SS * HID];
__device__ float g_wqc[(size_t)HID * NH * DH];
__device__ float g_wkc[(size_t)HID * NKV * DH];
__device__ float g_wvc[(size_t)HID * NKV * DH];
__device__ float g_woc[(size_t)NH * DH * HID];

__device__ __forceinline__ unsigned f2tf(float f) {
    unsigned u;
    asm("cvt.rna.tf32.f32 %0, %1;" : "=r"(u) : "f"(f));
    return u;
}
__device__ __forceinline__ float rndf(float f) { return __uint_as_float(f2tf(f)); }

__device__ __forceinline__ void cp16(void* smem, const void* gmem) {
    unsigned saddr = (unsigned)__cvta_generic_to_shared(smem);
    asm volatile("cp.async.ca.shared.global [%0], [%1], 16;\n"
                 :: "r"(saddr), "l"(gmem));
}
#define CP_COMMIT() asm volatile("cp.async.commit_group;\n" ::)
#define CP_WAIT0()  asm volatile("cp.async.wait_group 0;\n" ::)
#define CP_WAIT1()  asm volatile("cp.async.wait_group 1;\n" ::)

#define MMA_TF32(c, a, b) \
    asm volatile( \
        "mma.sync.aligned.m16n8k8.row.col.f32.tf32.tf32.f32 " \
        "{%0,%1,%2,%3}, {%4,%5,%6,%7}, {%8,%9}, {%0,%1,%2,%3};\n" \
        : "+f"((c)[0]), "+f"((c)[1]), "+f"((c)[2]), "+f"((c)[3]) \
        : "r"((a)[0]), "r"((a)[1]), "r"((a)[2]), "r"((a)[3]), \
          "r"((b)[0]), "r"((b)[1]))

// ---------------------------------------------------------------------------
// tf32 pre-rounding pass: one launch, blockIdx.y selects tensor.
// ---------------------------------------------------------------------------
__global__ __launch_bounds__(256) void cvt_tf32_all(
    const float4* __restrict__ s0, const float4* __restrict__ s1,
    const float4* __restrict__ s2, const float4* __restrict__ s3,
    const float4* __restrict__ s4)
{
    const float4* src;
    float4* dst;
    int n4;
    switch (blockIdx.y) {
        case 0: src = s0; dst = (float4*)g_xc;  n4 = (BB * SS * HID) / 4; break;
        case 1: src = s1; dst = (float4*)g_wqc; n4 = (HID * NH * DH) / 4; break;
        case 2: src = s2; dst = (float4*)g_wkc; n4 = (HID * NKV * DH) / 4; break;
        case 3: src = s3; dst = (float4*)g_wvc; n4 = (HID * NKV * DH) / 4; break;
        default: src = s4; dst = (float4*)g_woc; n4 = (NH * DH * HID) / 4; break;
    }
    int i = blockIdx.x * blockDim.x + threadIdx.x;
    if (i < n4) {
        float4 v = src[i];
        dst[i] = make_float4(rndf(v.x), rndf(v.y), rndf(v.z), rndf(v.w));
    }
}

// ---------------------------------------------------------------------------
// TF32 GEMM: 128x128 block, 4 warps (128 thr), 64x64 warp tile, BK=32,
// cp.async 3-stage ring (wait_group 1 steady state). Inputs pre-rounded.
// mode: 0 = plain store, 1 = rope+round, 2 = rope+scale+round (Q), 3 = round.
// ---------------------------------------------------------------------------
#define GA_W (128 * 36)
#define GB_W (32 * 132)
#define GST_W (GA_W + GB_W)
#define GEMM_SMEM_BYTES (3 * GST_W * 4)

__device__ __forceinline__ void gemm_body(
    const float* __restrict__ A, const float* __restrict__ W,
    float* __restrict__ C, int m0, int n0, int N, int K, int mode,
    float* gsm)
{
    const int tid = threadIdx.x;
    const int warp = tid >> 5, lane = tid & 31;
    const int g = lane >> 2, ct = lane & 3;
    const int wm = warp >> 1, wn = warp & 1;

    float c[4][8][4];
#pragma unroll
    for (int mt = 0; mt < 4; ++mt)
#pragma unroll
        for (int nt = 0; nt < 8; ++nt)
#pragma unroll
            for (int i = 0; i < 4; ++i) c[mt][nt][i] = 0.f;

    const int a0 = tid >> 3;             // A rows: a0 + 16*i (i<8)
    const int ak = (tid & 7) * 4;        // A k-offset
    const int b0 = tid >> 5;             // B rows: b0 + 4*i (i<8)
    const int bc = (tid & 31) * 4;       // B n-offset

    const int niter = K / 32;

    // prologue: issue stages 0 and 1
#pragma unroll
    for (int ps = 0; ps < 2; ++ps) {
        float* sA = gsm + ps * GST_W;
        float* sB = sA + GA_W;
        const int k0 = ps * 32;
#pragma unroll
        for (int i = 0; i < 8; ++i) {
            cp16(&sA[(a0 + i * 16) * 36 + ak],
                 A + (size_t)(m0 + a0 + i * 16) * K + k0 + ak);
            cp16(&sB[(b0 + i * 4) * 132 + bc],
                 W + (size_t)(k0 + b0 + i * 4) * N + n0 + bc);
        }
        CP_COMMIT();
    }

    int buf = 0, nbuf = 2;               // buf for iter it; nbuf = (it+2)%3
    for (int it = 0; it < niter; ++it) {
        if (it + 1 < niter) CP_WAIT1(); else CP_WAIT0();
        __syncthreads();

        if (it + 2 < niter) {
            const int k0 = (it + 2) * 32;
            float* sA = gsm + nbuf * GST_W;
            float* sB = sA + GA_W;
#pragma unroll
            for (int i = 0; i < 8; ++i) {
                cp16(&sA[(a0 + i * 16) * 36 + ak],
                     A + (size_t)(m0 + a0 + i * 16) * K + k0 + ak);
                cp16(&sB[(b0 + i * 4) * 132 + bc],
                     W + (size_t)(k0 + b0 + i * 4) * N + n0 + bc);
            }
            CP_COMMIT();
        }

        const unsigned* cA = (const unsigned*)(gsm + buf * GST_W);
        const unsigned* cB = cA + GA_W;
#pragma unroll
        for (int ks = 0; ks < 4; ++ks) {
            const int kk = ks * 8;
            unsigned a[4][4], b[8][2];
#pragma unroll
            for (int mt = 0; mt < 4; ++mt) {
                int r = wm * 64 + mt * 16;
                a[mt][0] = cA[(r + g) * 36 + kk + ct];
                a[mt][1] = cA[(r + g + 8) * 36 + kk + ct];
                a[mt][2] = cA[(r + g) * 36 + kk + ct + 4];
                a[mt][3] = cA[(r + g + 8) * 36 + kk + ct + 4];
            }
#pragma unroll
            for (int nt = 0; nt < 8; ++nt) {
                int cb = wn * 64 + nt * 8;
                b[nt][0] = cB[(kk + ct) * 132 + cb + g];
                b[nt][1] = cB[(kk + ct + 4) * 132 + cb + g];
            }
#pragma unroll
            for (int mt = 0; mt < 4; ++mt)
#pragma unroll
                for (int nt = 0; nt < 8; ++nt)
                    MMA_TF32(c[mt][nt], a[mt], b[nt]);
        }

        buf = (buf == 2) ? 0 : buf + 1;
        nbuf = (nbuf == 2) ? 0 : nbuf + 1;
    }

    if (mode == 0 || mode == 3) {
#pragma unroll
        for (int mt = 0; mt < 4; ++mt)
#pragma unroll
            for (int nt = 0; nt < 8; ++nt) {
                int row = m0 + wm * 64 + mt * 16 + g;
                int col = n0 + wn * 64 + nt * 8 + 2 * ct;
                float v0 = c[mt][nt][0], v1 = c[mt][nt][1];
                float v2 = c[mt][nt][2], v3 = c[mt][nt][3];
                if (mode == 3) { v0 = rndf(v0); v1 = rndf(v1); v2 = rndf(v2); v3 = rndf(v3); }
                *(float2*)(C + (size_t)row * N + col) = make_float2(v0, v1);
                *(float2*)(C + (size_t)(row + 8) * N + col) = make_float2(v2, v3);
            }
    } else {
        // Fused RoPE epilogue (+ optional 1/sqrt(D) scale), tf32-rounded out.
        const float sc = (mode == 2) ? 0.08838834764831845f : 1.0f;
#pragma unroll
        for (int nt = 0; nt < 8; ++nt) {
            int col = n0 + wn * 64 + nt * 8 + 2 * ct;      // even
            int i = (col & 127) >> 1;
            int hb = col & ~127;
            float inv = powf(10000.0f, -(2.0f * i) / 128.0f);
#pragma unroll
            for (int mt = 0; mt < 4; ++mt) {
                int row = m0 + wm * 64 + mt * 16 + g;
                float sn, cs;
                sincosf((float)(row & (SS - 1)) * inv, &sn, &cs);
                float x1 = c[mt][nt][0], x2 = c[mt][nt][1];
                C[(size_t)row * N + hb + i]      = rndf((x1 * cs - x2 * sn) * sc);
                C[(size_t)row * N + hb + i + 64] = rndf((x1 * sn + x2 * cs) * sc);
                sincosf((float)((row + 8) & (SS - 1)) * inv, &sn, &cs);
                x1 = c[mt][nt][2]; x2 = c[mt][nt][3];
                C[(size_t)(row + 8) * N + hb + i]      = rndf((x1 * cs - x2 * sn) * sc);
                C[(size_t)(row + 8) * N + hb + i + 64] = rndf((x1 * sn + x2 * cs) * sc);
            }
        }
    }
}

// Fused QKV projection: grid (24, 32). Blocks 0-15 -> Q (rope+scale),
// 16-19 -> K (rope), 20-23 -> V (round).
__global__ __launch_bounds__(128, 2) void gemm_qkv()
{
    extern __shared__ float gsm[];
    const int bx = blockIdx.x;
    const float* W;
    float* C;
    int N, n0, mode;
    if (bx < 16)      { W = g_wqc; C = g_q; N = NH * DH;  n0 = bx * 128;        mode = 2; }
    else if (bx < 20) { W = g_wkc; C = g_k; N = NKV * DH; n0 = (bx - 16) * 128; mode = 1; }
    else              { W = g_wvc; C = g_v; N = NKV * DH; n0 = (bx - 20) * 128; mode = 3; }
    gemm_body(g_xc, W, C, blockIdx.y * 128, n0, N, HID, mode, gsm);
}

// Output projection (plain fp32 store)
__global__ __launch_bounds__(128, 2) void gemm_out(float* __restrict__ C)
{
    extern __shared__ float gsm[];
    gemm_body(g_o, g_woc, C, blockIdx.y * 128, blockIdx.x * 128,
              HID, NH * DH, 0, gsm);
}

// ---------------------------------------------------------------------------
// Flash attention: pre-rounded inputs; K/V staged via cp.async ping-pong,
// second buffer aliased onto the dead sQ region (Q lives in registers after
// the fragment preload). One __syncthreads per tile.  (unchanged from R11)
// ---------------------------------------------------------------------------
#define ATTN_SMEM_WORDS (128 * 132 + 2 * 64 * 132 + 128 * 68)
#define ATTN_SMEM_BYTES (ATTN_SMEM_WORDS * 4)

__global__ __launch_bounds__(256) void attn_tc(
    const float* __restrict__ Q, const float* __restrict__ K,
    const float* __restrict__ V, float* __restrict__ O)
{
    extern __shared__ unsigned smu[];
    unsigned* sQ = smu;                       // [row][d] stride 132 (dies early)
    unsigned* sP = smu + 33792;               // [row][key] stride 68
    unsigned* kb[2] = { smu + 16896, smu + 0 };
    unsigned* vb[2] = { smu + 25344, smu + 8448 };

    const int tid = threadIdx.x;
    const int warp = tid >> 5, lane = tid & 31;
    const int g = lane >> 2, ct = lane & 3;
    const int bh = blockIdx.y;
    const int b = bh / NH, h = bh % NH;
    const int kvh = h / REP;
    const int qt = (gridDim.x - 1) - blockIdx.x;    // heavy tiles first
    const int q0 = qt * 128;

    // Stage Q (pre-scaled, pre-rounded): raw copies
#pragma unroll
    for (int i = 0; i < 16; ++i) {
        int f4 = tid + i * 256;
        int row = f4 >> 5;
        int c4 = (f4 & 31) * 4;
        *(uint4*)&sQ[row * 132 + c4] =
            *(const uint4*)(Q + ((size_t)(b * SS + q0 + row) * NH + h) * DH + c4);
    }
    __syncthreads();

    const int rbase = 16 * warp;

    // Preload Q fragments for all 16 k-slices; sQ is dead afterwards.
    unsigned qa[16][4];
#pragma unroll
    for (int ks = 0; ks < 16; ++ks) {
        const int kk = ks * 8;
        qa[ks][0] = sQ[(rbase + g) * 132 + kk + ct];
        qa[ks][1] = sQ[(rbase + g + 8) * 132 + kk + ct];
        qa[ks][2] = sQ[(rbase + g) * 132 + kk + ct + 4];
        qa[ks][3] = sQ[(rbase + g + 8) * 132 + kk + ct + 4];
    }

    // Issue tile 0 into buffer 0 (region untouched by Q staging/preload)
    {
#pragma unroll
        for (int i = 0; i < 8; ++i) {
            int f4 = tid + i * 256;
            int row = f4 >> 5;
            int c4 = (f4 & 31) * 4;
            size_t base = ((size_t)(b * SS + row) * NKV + kvh) * DH + c4;
            cp16(&kb[0][row * 132 + c4], K + base);
            cp16(&vb[0][row * 132 + c4], V + base);
        }
        CP_COMMIT();
    }

    float m_prev[2] = {-1e30f, -1e30f};
    float lsum[2] = {0.f, 0.f};
    float o[16][4];
#pragma unroll
    for (int nt = 0; nt < 16; ++nt)
#pragma unroll
        for (int i = 0; i < 4; ++i) o[nt][i] = 0.f;

    const int tmax = (q0 + 128) / 64;

    for (int t = 0; t < tmax; ++t) {
        const int k0g = t * 64;
        CP_WAIT0();
        __syncthreads();

        if (t + 1 < tmax) {
            const int kn = (t + 1) * 64;
            const int st = (t + 1) & 1;
#pragma unroll
            for (int i = 0; i < 8; ++i) {
                int f4 = tid + i * 256;
                int row = f4 >> 5;
                int c4 = (f4 & 31) * 4;
                size_t base = ((size_t)(b * SS + kn + row) * NKV + kvh) * DH + c4;
                cp16(&kb[st][row * 132 + c4], K + base);
                cp16(&vb[st][row * 132 + c4], V + base);
            }
            CP_COMMIT();
        }

        const unsigned* sK = kb[t & 1];
        const unsigned* sV = vb[t & 1];

        float s[8][4];
#pragma unroll
        for (int nt = 0; nt < 8; ++nt)
#pragma unroll
            for (int i = 0; i < 4; ++i) s[nt][i] = 0.f;

#pragma unroll
        for (int ks = 0; ks < 16; ++ks) {
            const int kk = ks * 8;
            unsigned bfr[8][2];
#pragma unroll
            for (int nt = 0; nt < 8; ++nt) {
                bfr[nt][0] = sK[(nt * 8 + g) * 132 + kk + ct];
                bfr[nt][1] = sK[(nt * 8 + g) * 132 + kk + ct + 4];
            }
#pragma unroll
            for (int nt = 0; nt < 8; ++nt)
                MMA_TF32(s[nt], qa[ks], bfr[nt]);
        }

        if (k0g + 63 > q0 + rbase) {
            int row0 = q0 + rbase + g;
#pragma unroll
            for (int nt = 0; nt < 8; ++nt) {
                int col = k0g + nt * 8 + 2 * ct;
                if (col > row0)         s[nt][0] = -1e30f;
                if (col + 1 > row0)     s[nt][1] = -1e30f;
                if (col > row0 + 8)     s[nt][2] = -1e30f;
                if (col + 1 > row0 + 8) s[nt][3] = -1e30f;
            }
        }

        float resc[2];
#pragma unroll
        for (int r = 0; r < 2; ++r) {
            float mt = -1e30f;
#pragma unroll
            for (int nt = 0; nt < 8; ++nt)
                mt = fmaxf(mt, fmaxf(s[nt][2 * r], s[nt][2 * r + 1]));
            mt = fmaxf(mt, __shfl_xor_sync(0xffffffffu, mt, 1));
            mt = fmaxf(mt, __shfl_xor_sync(0xffffffffu, mt, 2));
            float m_new = fmaxf(m_prev[r], mt);
            resc[r] = __expf(m_prev[r] - m_new);
            float lt = 0.f;
#pragma unroll
            for (int nt = 0; nt < 8; ++nt) {
                float p0 = __expf(s[nt][2 * r] - m_new);
                float p1 = __expf(s[nt][2 * r + 1] - m_new);
                s[nt][2 * r] = p0;
                s[nt][2 * r + 1] = p1;
                lt += p0 + p1;
            }
            lt += __shfl_xor_sync(0xffffffffu, lt, 1);
            lt += __shfl_xor_sync(0xffffffffu, lt, 2);
            lsum[r] = lsum[r] * resc[r] + lt;
            m_prev[r] = m_new;
        }
#pragma unroll
        for (int nt = 0; nt < 16; ++nt) {
            o[nt][0] *= resc[0];
            o[nt][1] *= resc[0];
            o[nt][2] *= resc[1];
            o[nt][3] *= resc[1];
        }
#pragma unroll
        for (int nt = 0; nt < 8; ++nt) {
            *(uint2*)&sP[(rbase + g) * 68 + nt * 8 + 2 * ct] =
                make_uint2(f2tf(s[nt][0]), f2tf(s[nt][1]));
            *(uint2*)&sP[(rbase + g + 8) * 68 + nt * 8 + 2 * ct] =
                make_uint2(f2tf(s[nt][2]), f2tf(s[nt][3]));
        }
        __syncwarp();

#pragma unroll
        for (int ks = 0; ks < 8; ++ks) {
            const int kk = ks * 8;
            unsigned a[4];
            a[0] = sP[(rbase + g) * 68 + kk + ct];
            a[1] = sP[(rbase + g + 8) * 68 + kk + ct];
            a[2] = sP[(rbase + g) * 68 + kk + ct + 4];
            a[3] = sP[(rbase + g + 8) * 68 + kk + ct + 4];
#pragma unroll
            for (int nt = 0; nt < 16; ++nt) {
                unsigned bfr[2];
                bfr[0] = sV[(kk + ct) * 132 + nt * 8 + g];
                bfr[1] = sV[(kk + ct + 4) * 132 + nt * 8 + g];
                MMA_TF32(o[nt], a, bfr);
            }
        }
    }

    // Epilogue: normalize, tf32-round (input to the Wo GEMM), write out.
    float inv0 = 1.0f / lsum[0];
    float inv1 = 1.0f / lsum[1];
    int row0 = q0 + rbase + g;
#pragma unroll
    for (int nt = 0; nt < 16; ++nt) {
        int col = nt * 8 + 2 * ct;
        size_t b0a = ((size_t)(b * SS + row0) * NH + h) * DH + col;
        size_t b1a = ((size_t)(b * SS + row0 + 8) * NH + h) * DH + col;
        *(float2*)(O + b0a) =
            make_float2(rndf(o[nt][0] * inv0), rndf(o[nt][1] * inv0));
        *(float2*)(O + b1a) =
            make_float2(rndf(o[nt][2] * inv1), rndf(o[nt][3] * inv1));
    }
}

// ---------------------------------------------------------------------------
// Launch
// ---------------------------------------------------------------------------
extern "C" void kernel_launch(void* const* d_in, const int* in_sizes, int n_in,
                              void* d_out, int out_size)
{
    const float* x  = (const float*)d_in[0];
    const float* Wq = (const float*)d_in[2];
    const float* Wk = (const float*)d_in[3];
    const float* Wv = (const float*)d_in[4];
    const float* Wo = (const float*)d_in[5];
    float* out = (float*)d_out;

    float *q, *k, *v, *o;
    cudaGetSymbolAddress((void**)&q, g_q);
    cudaGetSymbolAddress((void**)&k, g_k);
    cudaGetSymbolAddress((void**)&v, g_v);
    cudaGetSymbolAddress((void**)&o, g_o);

    const int M = BB * SS;   // 4096

    cudaFuncSetAttribute(gemm_qkv, cudaFuncAttributeMaxDynamicSharedMemorySize,
                         GEMM_SMEM_BYTES);
    cudaFuncSetAttribute(gemm_out, cudaFuncAttributeMaxDynamicSharedMemorySize,
                         GEMM_SMEM_BYTES);
    cudaFuncSetAttribute(attn_tc, cudaFuncAttributeMaxDynamicSharedMemorySize,
                         ATTN_SMEM_BYTES);

    // tf32 pre-rounding of all GEMM inputs (one launch; y selects tensor)
    {
        int max_n4 = (BB * SS * HID) / 4;                   // 2097152
        dim3 grid((max_n4 + 255) / 256, 5);
        cvt_tf32_all<<<grid, 256>>>((const float4*)x, (const float4*)Wq,
                                    (const float4*)Wk, (const float4*)Wv,
                                    (const float4*)Wo);
    }

    // Fused QKV projections (RoPE + scale + rounding fused into epilogues)
    gemm_qkv<<<dim3(24, M / 128), 128, GEMM_SMEM_BYTES>>>();

    // Flash attention
    attn_tc<<<dim3(SS / 128, BB * NH), 256, ATTN_SMEM_BYTES>>>(q, k, v, o);

    // Output projection
    gemm_out<<<dim3(HID / 128, M / 128), 128, GEMM_SMEM_BYTES>>>(out);
}

// round 15
// speedup vs baseline: 1.3173x; 1.3173x over previous
#include <cuda_runtime.h>
#include <cuda_fp16.h>
#include <math.h>
#include <stdint.h>

// Problem constants
#define BB 2
#define SS 2048
#define HID 2048
#define NH 16
#define NKV 4
#define DH 128
#define REP (NH / NKV)   // 4

// Scratch buffers
__device__ float g_q[(size_t)BB * SS * NH * DH];    // rope'd, scaled, tf32-rounded
__device__ float g_k[(size_t)BB * SS * NKV * DH];   // rope'd, tf32-rounded
__device__ float g_v[(size_t)BB * SS * NKV * DH];   // tf32-rounded
__device__ __half g_oh[(size_t)BB * SS * NH * DH];  // attn out, fp16
// fp16 GEMM operands
__device__ __half g_xh[(size_t)BB * SS * HID];          // x, [m][k]
__device__ __half g_wqt[(size_t)NH * DH * HID];         // Wq^T, [n][k]
__device__ __half g_wkt[(size_t)NKV * DH * HID];        // Wk^T
__device__ __half g_wvt[(size_t)NKV * DH * HID];        // Wv^T
__device__ __half g_wot[(size_t)HID * NH * DH];         // Wo^T, [n][k]

__device__ __forceinline__ unsigned f2tf(float f) {
    unsigned u;
    asm("cvt.rna.tf32.f32 %0, %1;" : "=r"(u) : "f"(f));
    return u;
}
__device__ __forceinline__ float rndf(float f) { return __uint_as_float(f2tf(f)); }

__device__ __forceinline__ void cp16(void* smem, const void* gmem) {
    unsigned saddr = (unsigned)__cvta_generic_to_shared(smem);
    asm volatile("cp.async.ca.shared.global [%0], [%1], 16;\n"
                 :: "r"(saddr), "l"(gmem));
}
#define CP_COMMIT() asm volatile("cp.async.commit_group;\n" ::)
#define CP_WAIT0()  asm volatile("cp.async.wait_group 0;\n" ::)

// warp-level tf32 mma (attention)
#define MMA_TF32(c, a, b) \
    asm volatile( \
        "mma.sync.aligned.m16n8k8.row.col.f32.tf32.tf32.f32 " \
        "{%0,%1,%2,%3}, {%4,%5,%6,%7}, {%8,%9}, {%0,%1,%2,%3};\n" \
        : "+f"((c)[0]), "+f"((c)[1]), "+f"((c)[2]), "+f"((c)[3]) \
        : "r"((a)[0]), "r"((a)[1]), "r"((a)[2]), "r"((a)[3]), \
          "r"((b)[0]), "r"((b)[1]))

// warp-level fp16 mma, fp32 accum (GEMMs)
#define MMA_F16(c, a, b) \
    asm volatile( \
        "mma.sync.aligned.m16n8k16.row.col.f32.f16.f16.f32 " \
        "{%0,%1,%2,%3}, {%4,%5,%6,%7}, {%8,%9}, {%0,%1,%2,%3};\n" \
        : "+f"((c)[0]), "+f"((c)[1]), "+f"((c)[2]), "+f"((c)[3]) \
        : "r"((a)[0]), "r"((a)[1]), "r"((a)[2]), "r"((a)[3]), \
          "r"((b)[0]), "r"((b)[1]))

// ---------------------------------------------------------------------------
// Prep: z=0 converts x -> fp16; z=1..4 transpose-convert weights -> [n][k] fp16.
// Grid (64, 64, 5), block (32, 8).
// ---------------------------------------------------------------------------
__global__ __launch_bounds__(256) void prep_half(
    const float* __restrict__ x,  const float* __restrict__ Wq,
    const float* __restrict__ Wk, const float* __restrict__ Wv,
    const float* __restrict__ Wo)
{
    const int z = blockIdx.z;
    const int tx = threadIdx.x, ty = threadIdx.y;
    if (z == 0) {
        // x: 8M floats = 2M float4; 4096 blocks x 256 thr x 2
        int base = (blockIdx.y * gridDim.x + blockIdx.x) * 256 + ty * 32 + tx;
        __half2* dst = (__half2*)g_xh;
#pragma unroll
        for (int r = 0; r < 2; ++r) {
            int i = base + r * 1048576;
            float4 v = ((const float4*)x)[i];
            dst[2 * i]     = __floats2half2_rn(v.x, v.y);
            dst[2 * i + 1] = __floats2half2_rn(v.z, v.w);
        }
        return;
    }
    const float* src;
    __half* dst;
    int N;
    switch (z) {
        case 1:  src = Wq; dst = g_wqt; N = NH * DH;  break;
        case 2:  src = Wk; dst = g_wkt; N = NKV * DH; break;
        case 3:  src = Wv; dst = g_wvt; N = NKV * DH; break;
        default: src = Wo; dst = g_wot; N = HID;      break;
    }
    int kk = blockIdx.x * 32, nn = blockIdx.y * 32;
    if (nn >= N) return;
    __shared__ float tb[32][33];
#pragma unroll
    for (int i = 0; i < 4; ++i)
        tb[ty + 8 * i][tx] = src[(size_t)(kk + ty + 8 * i) * N + nn + tx];
    __syncthreads();
#pragma unroll
    for (int i = 0; i < 4; ++i)
        dst[(size_t)(nn + ty + 8 * i) * HID + kk + tx] =
            __float2half_rn(tb[tx][ty + 8 * i]);
}

// ---------------------------------------------------------------------------
// FP16 GEMM: C[*,N](+n0) = A[M,K]@B^T (B given as Bt[n][k] fp16).
// 128x128 block, 4 warps, 64x64 warp tile, BK=32 halves, cp.async 2-stage.
// smem word layout per buffer: 128 rows x 20 words (16 data + 4 pad) = 10240B.
// mode: 0 plain fp32, 1 rope+tf32round (K), 2 rope+scale+tf32round (Q),
//       3 tf32round (V).
// ---------------------------------------------------------------------------
#define HB_W 2560                       // words per buffer (128*20)
#define GEMM_SMEM_BYTES (4 * HB_W * 4)  // A0 A1 B0 B1 = 40960

__device__ __forceinline__ void gemm_body(
    const __half* __restrict__ A, const __half* __restrict__ Bt,
    float* __restrict__ C, int m0, int n0, int N, int K, int mode,
    unsigned* gsm)
{
    unsigned* bufs[4] = {gsm, gsm + HB_W, gsm + 2 * HB_W, gsm + 3 * HB_W};

    const int tid = threadIdx.x;
    const int warp = tid >> 5, lane = tid & 31;
    const int g = lane >> 2, ct = lane & 3;
    const int wm = warp >> 1, wn = warp & 1;

    float c[4][8][4];
#pragma unroll
    for (int mt = 0; mt < 4; ++mt)
#pragma unroll
        for (int nt = 0; nt < 8; ++nt)
#pragma unroll
            for (int i = 0; i < 4; ++i) c[mt][nt][i] = 0.f;

    // staging: granule gid = tid + 128*i (i<4): row = gid>>2, word off = (gid&3)*4
    const int srow = tid >> 2;
    const int sgw = (tid & 3) * 4;
    const int niter = K / 32;

    // stage 0
#pragma unroll
    for (int i = 0; i < 4; ++i) {
        int row = srow + 32 * i;
        cp16(&bufs[0][row * 20 + sgw], A + (size_t)(m0 + row) * K + sgw * 2);
        cp16(&bufs[2][row * 20 + sgw], Bt + (size_t)(n0 + row) * K + sgw * 2);
    }
    CP_COMMIT();

    for (int it = 0; it < niter; ++it) {
        CP_WAIT0();
        __syncthreads();

        if (it + 1 < niter) {
            const int k0 = (it + 1) * 32;
            const int st = (it + 1) & 1;
#pragma unroll
            for (int i = 0; i < 4; ++i) {
                int row = srow + 32 * i;
                cp16(&bufs[st][row * 20 + sgw],
                     A + (size_t)(m0 + row) * K + k0 + sgw * 2);
                cp16(&bufs[2 + st][row * 20 + sgw],
                     Bt + (size_t)(n0 + row) * K + k0 + sgw * 2);
            }
            CP_COMMIT();
        }

        const unsigned* cA = bufs[it & 1];
        const unsigned* cB = bufs[2 + (it & 1)];
#pragma unroll
        for (int ks = 0; ks < 2; ++ks) {
            const int kw = ks * 8;
            unsigned a[4][4], b[8][2];
#pragma unroll
            for (int mt = 0; mt < 4; ++mt) {
                int r = wm * 64 + mt * 16;
                a[mt][0] = cA[(r + g) * 20 + kw + ct];
                a[mt][1] = cA[(r + g + 8) * 20 + kw + ct];
                a[mt][2] = cA[(r + g) * 20 + kw + ct + 4];
                a[mt][3] = cA[(r + g + 8) * 20 + kw + ct + 4];
            }
#pragma unroll
            for (int nt = 0; nt < 8; ++nt) {
                int nb = wn * 64 + nt * 8;
                b[nt][0] = cB[(nb + g) * 20 + kw + ct];
                b[nt][1] = cB[(nb + g) * 20 + kw + ct + 4];
            }
#pragma unroll
            for (int mt = 0; mt < 4; ++mt)
#pragma unroll
                for (int nt = 0; nt < 8; ++nt)
                    MMA_F16(c[mt][nt], a[mt], b[nt]);
        }
    }

    if (mode == 0 || mode == 3) {
#pragma unroll
        for (int mt = 0; mt < 4; ++mt)
#pragma unroll
            for (int nt = 0; nt < 8; ++nt) {
                int row = m0 + wm * 64 + mt * 16 + g;
                int col = n0 + wn * 64 + nt * 8 + 2 * ct;
                float v0 = c[mt][nt][0], v1 = c[mt][nt][1];
                float v2 = c[mt][nt][2], v3 = c[mt][nt][3];
                if (mode == 3) { v0 = rndf(v0); v1 = rndf(v1); v2 = rndf(v2); v3 = rndf(v3); }
                *(float2*)(C + (size_t)row * N + col) = make_float2(v0, v1);
                *(float2*)(C + (size_t)(row + 8) * N + col) = make_float2(v2, v3);
            }
    } else {
        const float sc = (mode == 2) ? 0.08838834764831845f : 1.0f;
#pragma unroll
        for (int nt = 0; nt < 8; ++nt) {
            int col = n0 + wn * 64 + nt * 8 + 2 * ct;      // even
            int i = (col & 127) >> 1;
            int hb = col & ~127;
            float inv = powf(10000.0f, -(2.0f * i) / 128.0f);
#pragma unroll
            for (int mt = 0; mt < 4; ++mt) {
                int row = m0 + wm * 64 + mt * 16 + g;
                float sn, cs;
                sincosf((float)(row & (SS - 1)) * inv, &sn, &cs);
                float x1 = c[mt][nt][0], x2 = c[mt][nt][1];
                C[(size_t)row * N + hb + i]      = rndf((x1 * cs - x2 * sn) * sc);
                C[(size_t)row * N + hb + i + 64] = rndf((x1 * sn + x2 * cs) * sc);
                sincosf((float)((row + 8) & (SS - 1)) * inv, &sn, &cs);
                x1 = c[mt][nt][2]; x2 = c[mt][nt][3];
                C[(size_t)(row + 8) * N + hb + i]      = rndf((x1 * cs - x2 * sn) * sc);
                C[(size_t)(row + 8) * N + hb + i + 64] = rndf((x1 * sn + x2 * cs) * sc);
            }
        }
    }
}

// Fused QKV projection: grid (24, 32). 0-15 Q (rope+scale), 16-19 K (rope),
// 20-23 V (round).
__global__ __launch_bounds__(128, 2) void gemm_qkv()
{
    extern __shared__ unsigned gsm[];
    const int bx = blockIdx.x;
    const __half* Bt;
    float* C;
    int N, n0, mode;
    if (bx < 16)      { Bt = g_wqt; C = g_q; N = NH * DH;  n0 = bx * 128;        mode = 2; }
    else if (bx < 20) { Bt = g_wkt; C = g_k; N = NKV * DH; n0 = (bx - 16) * 128; mode = 1; }
    else              { Bt = g_wvt; C = g_v; N = NKV * DH; n0 = (bx - 20) * 128; mode = 3; }
    gemm_body(g_xh, Bt, C, blockIdx.y * 128, n0, N, HID, mode, gsm);
}

// Output projection
__global__ __launch_bounds__(128, 2) void gemm_out(float* __restrict__ C)
{
    extern __shared__ unsigned gsm[];
    gemm_body(g_oh, g_wot, C, blockIdx.y * 128, blockIdx.x * 128,
              HID, NH * DH, 0, gsm);
}

// ---------------------------------------------------------------------------
// Flash attention (R11-proven): cp.async ping-pong K/V aliased on dead sQ;
// warp-mma TF32; Q fragments in registers. Epilogue now emits fp16 o.
// ---------------------------------------------------------------------------
#define ATTN_SMEM_WORDS (128 * 132 + 2 * 64 * 132 + 128 * 68)
#define ATTN_SMEM_BYTES (ATTN_SMEM_WORDS * 4)

__global__ __launch_bounds__(256) void attn_tc(
    const float* __restrict__ Q, const float* __restrict__ K,
    const float* __restrict__ V, __half* __restrict__ O)
{
    extern __shared__ unsigned smu[];
    unsigned* sQ = smu;
    unsigned* sP = smu + 33792;
    unsigned* kb[2] = { smu + 16896, smu + 0 };
    unsigned* vb[2] = { smu + 25344, smu + 8448 };

    const int tid = threadIdx.x;
    const int warp = tid >> 5, lane = tid & 31;
    const int g = lane >> 2, ct = lane & 3;
    const int bh = blockIdx.y;
    const int b = bh / NH, h = bh % NH;
    const int kvh = h / REP;
    const int qt = (gridDim.x - 1) - blockIdx.x;
    const int q0 = qt * 128;

#pragma unroll
    for (int i = 0; i < 16; ++i) {
        int f4 = tid + i * 256;
        int row = f4 >> 5;
        int c4 = (f4 & 31) * 4;
        *(uint4*)&sQ[row * 132 + c4] =
            *(const uint4*)(Q + ((size_t)(b * SS + q0 + row) * NH + h) * DH + c4);
    }
    __syncthreads();

    const int rbase = 16 * warp;

    unsigned qa[16][4];
#pragma unroll
    for (int ks = 0; ks < 16; ++ks) {
        const int kk = ks * 8;
        qa[ks][0] = sQ[(rbase + g) * 132 + kk + ct];
        qa[ks][1] = sQ[(rbase + g + 8) * 132 + kk + ct];
        qa[ks][2] = sQ[(rbase + g) * 132 + kk + ct + 4];
        qa[ks][3] = sQ[(rbase + g + 8) * 132 + kk + ct + 4];
    }

    {
#pragma unroll
        for (int i = 0; i < 8; ++i) {
            int f4 = tid + i * 256;
            int row = f4 >> 5;
            int c4 = (f4 & 31) * 4;
            size_t base = ((size_t)(b * SS + row) * NKV + kvh) * DH + c4;
            cp16(&kb[0][row * 132 + c4], K + base);
            cp16(&vb[0][row * 132 + c4], V + base);
        }
        CP_COMMIT();
    }

    float m_prev[2] = {-1e30f, -1e30f};
    float lsum[2] = {0.f, 0.f};
    float o[16][4];
#pragma unroll
    for (int nt = 0; nt < 16; ++nt)
#pragma unroll
        for (int i = 0; i < 4; ++i) o[nt][i] = 0.f;

    const int tmax = (q0 + 128) / 64;

    for (int t = 0; t < tmax; ++t) {
        const int k0g = t * 64;
        CP_WAIT0();
        __syncthreads();

        if (t + 1 < tmax) {
            const int kn = (t + 1) * 64;
            const int st = (t + 1) & 1;
#pragma unroll
            for (int i = 0; i < 8; ++i) {
                int f4 = tid + i * 256;
                int row = f4 >> 5;
                int c4 = (f4 & 31) * 4;
                size_t base = ((size_t)(b * SS + kn + row) * NKV + kvh) * DH + c4;
                cp16(&kb[st][row * 132 + c4], K + base);
                cp16(&vb[st][row * 132 + c4], V + base);
            }
            CP_COMMIT();
        }

        const unsigned* sK = kb[t & 1];
        const unsigned* sV = vb[t & 1];

        float s[8][4];
#pragma unroll
        for (int nt = 0; nt < 8; ++nt)
#pragma unroll
            for (int i = 0; i < 4; ++i) s[nt][i] = 0.f;

#pragma unroll
        for (int ks = 0; ks < 16; ++ks) {
            const int kk = ks * 8;
            unsigned bfr[8][2];
#pragma unroll
            for (int nt = 0; nt < 8; ++nt) {
                bfr[nt][0] = sK[(nt * 8 + g) * 132 + kk + ct];
                bfr[nt][1] = sK[(nt * 8 + g) * 132 + kk + ct + 4];
            }
#pragma unroll
            for (int nt = 0; nt < 8; ++nt)
                MMA_TF32(s[nt], qa[ks], bfr[nt]);
        }

        if (k0g + 63 > q0 + rbase) {
            int row0 = q0 + rbase + g;
#pragma unroll
            for (int nt = 0; nt < 8; ++nt) {
                int col = k0g + nt * 8 + 2 * ct;
                if (col > row0)         s[nt][0] = -1e30f;
                if (col + 1 > row0)     s[nt][1] = -1e30f;
                if (col > row0 + 8)     s[nt][2] = -1e30f;
                if (col + 1 > row0 + 8) s[nt][3] = -1e30f;
            }
        }

        float resc[2];
#pragma unroll
        for (int r = 0; r < 2; ++r) {
            float mt = -1e30f;
#pragma unroll
            for (int nt = 0; nt < 8; ++nt)
                mt = fmaxf(mt, fmaxf(s[nt][2 * r], s[nt][2 * r + 1]));
            mt = fmaxf(mt, __shfl_xor_sync(0xffffffffu, mt, 1));
            mt = fmaxf(mt, __shfl_xor_sync(0xffffffffu, mt, 2));
            float m_new = fmaxf(m_prev[r], mt);
            resc[r] = __expf(m_prev[r] - m_new);
            float lt = 0.f;
#pragma unroll
            for (int nt = 0; nt < 8; ++nt) {
                float p0 = __expf(s[nt][2 * r] - m_new);
                float p1 = __expf(s[nt][2 * r + 1] - m_new);
                s[nt][2 * r] = p0;
                s[nt][2 * r + 1] = p1;
                lt += p0 + p1;
            }
            lt += __shfl_xor_sync(0xffffffffu, lt, 1);
            lt += __shfl_xor_sync(0xffffffffu, lt, 2);
            lsum[r] = lsum[r] * resc[r] + lt;
            m_prev[r] = m_new;
        }
#pragma unroll
        for (int nt = 0; nt < 16; ++nt) {
            o[nt][0] *= resc[0];
            o[nt][1] *= resc[0];
            o[nt][2] *= resc[1];
            o[nt][3] *= resc[1];
        }
#pragma unroll
        for (int nt = 0; nt < 8; ++nt) {
            *(uint2*)&sP[(rbase + g) * 68 + nt * 8 + 2 * ct] =
                make_uint2(f2tf(s[nt][0]), f2tf(s[nt][1]));
            *(uint2*)&sP[(rbase + g + 8) * 68 + nt * 8 + 2 * ct] =
                make_uint2(f2tf(s[nt][2]), f2tf(s[nt][3]));
        }
        __syncwarp();

#pragma unroll
        for (int ks = 0; ks < 8; ++ks) {
            const int kk = ks * 8;
            unsigned a[4];
            a[0] = sP[(rbase + g) * 68 + kk + ct];
            a[1] = sP[(rbase + g + 8) * 68 + kk + ct];
            a[2] = sP[(rbase + g) * 68 + kk + ct + 4];
            a[3] = sP[(rbase + g + 8) * 68 + kk + ct + 4];
#pragma unroll
            for (int nt = 0; nt < 16; ++nt) {
                unsigned bfr[2];
                bfr[0] = sV[(kk + ct) * 132 + nt * 8 + g];
                bfr[1] = sV[(kk + ct + 4) * 132 + nt * 8 + g];
                MMA_TF32(o[nt], a, bfr);
            }
        }
    }

    // Epilogue: normalize, emit fp16 (input to the Wo fp16 GEMM).
    float inv0 = 1.0f / lsum[0];
    float inv1 = 1.0f / lsum[1];
    int row0 = q0 + rbase + g;
#pragma unroll
    for (int nt = 0; nt < 16; ++nt) {
        int col = nt * 8 + 2 * ct;
        size_t b0a = ((size_t)(b * SS + row0) * NH + h) * DH + col;
        size_t b1a = ((size_t)(b * SS + row0 + 8) * NH + h) * DH + col;
        *(__half2*)(O + b0a) = __floats2half2_rn(o[nt][0] * inv0, o[nt][1] * inv0);
        *(__half2*)(O + b1a) = __floats2half2_rn(o[nt][2] * inv1, o[nt][3] * inv1);
    }
}

// ---------------------------------------------------------------------------
// Launch
// ---------------------------------------------------------------------------
extern "C" void kernel_launch(void* const* d_in, const int* in_sizes, int n_in,
                              void* d_out, int out_size)
{
    const float* x  = (const float*)d_in[0];
    const float* Wq = (const float*)d_in[2];
    const float* Wk = (const float*)d_in[3];
    const float* Wv = (const float*)d_in[4];
    const float* Wo = (const float*)d_in[5];
    float* out = (float*)d_out;

    float *q, *k, *v;
    __half* oh;
    cudaGetSymbolAddress((void**)&q, g_q);
    cudaGetSymbolAddress((void**)&k, g_k);
    cudaGetSymbolAddress((void**)&v, g_v);
    cudaGetSymbolAddress((void**)&oh, g_oh);

    const int M = BB * SS;   // 4096

    cudaFuncSetAttribute(attn_tc, cudaFuncAttributeMaxDynamicSharedMemorySize,
                         ATTN_SMEM_BYTES);

    // fp16 conversion + weight transposes
    prep_half<<<dim3(64, 64, 5), dim3(32, 8)>>>(x, Wq, Wk, Wv, Wo);

    // Fused QKV projections (fp16 mma; RoPE/scale/round fused in epilogues)
    gemm_qkv<<<dim3(24, M / 128), 128, GEMM_SMEM_BYTES>>>();

    // Flash attention (tf32; emits fp16 o)
    attn_tc<<<dim3(SS / 128, BB * NH), 256, ATTN_SMEM_BYTES>>>(q, k, v, oh);

    // Output projection (fp16 mma)
    gemm_out<<<dim3(HID / 128, M / 128), 128, GEMM_SMEM_BYTES>>>(out);
}